// round 1
// baseline (speedup 1.0000x reference)
#include <cuda_runtime.h>
#include <cstdint>

// Problem constants
#define T_MSG 8
#define B_DIM 4
#define S_DIM 2048
#define N_TOK (B_DIM * S_DIM)      // 8192
#define LAT 1024
#define SYM 256
#define NC 512

// Output layout (float32): node_output | quantized | indices | keep_mask
#define OUT_NODE_OFF 0
#define OUT_QUANT_OFF ((size_t)N_TOK * LAT)                       // 8388608
#define OUT_IDX_OFF   (OUT_QUANT_OFF + (size_t)N_TOK * SYM)       // 10485760
#define OUT_KEEP_OFF  (OUT_IDX_OFF + (size_t)N_TOK)               // 10493952

// ---------------------------------------------------------------------------
// Device scratch (static allocation: allowed; cudaMalloc is not)
// ---------------------------------------------------------------------------
__device__ float g_bus_context[(size_t)N_TOK * LAT];   // 32 MB
__device__ float g_zread[(size_t)N_TOK * LAT];         // 32 MB
__device__ float g_h[(size_t)N_TOK * LAT];             // 32 MB
__device__ float g_raw[(size_t)N_TOK * SYM];           //  8 MB
__device__ float g_scores[(size_t)N_TOK * NC];         // 16 MB
__device__ float g_cnorm[NC];
__device__ int   g_used[T_MSG];

// ---------------------------------------------------------------------------
// 0) zero used-flags
// ---------------------------------------------------------------------------
__global__ void init_used_kernel() {
    if (threadIdx.x < T_MSG) g_used[threadIdx.x] = 0;
}

// ---------------------------------------------------------------------------
// 1) Routing: relevance = syms @ Wq + bq ; argmax over T ; gather bus_outputs
//    one block (256 threads) per token n
// ---------------------------------------------------------------------------
__global__ void routing_kernel(const float* __restrict__ bus_symbols,
                               const float* __restrict__ bus_outputs,
                               const float* __restrict__ Wq,
                               const float* __restrict__ bq) {
    int n = blockIdx.x;
    int tid = threadIdx.x;
    int lane = tid & 31, warp = tid >> 5;

    __shared__ float sWq[SYM];
    __shared__ float sRed[8];
    __shared__ int sTop;

    sWq[tid] = Wq[tid];
    __syncthreads();

    float best = -3.4e38f;
    int bt = 0;
    for (int t = 0; t < T_MSG; t++) {
        float v = bus_symbols[((size_t)t * N_TOK + n) * SYM + tid] * sWq[tid];
        // warp reduce
        #pragma unroll
        for (int off = 16; off > 0; off >>= 1)
            v += __shfl_down_sync(0xffffffffu, v, off);
        if (lane == 0) sRed[warp] = v;
        __syncthreads();
        if (tid == 0) {
            float r = sRed[0] + sRed[1] + sRed[2] + sRed[3]
                    + sRed[4] + sRed[5] + sRed[6] + sRed[7] + bq[0];
            if (r > best) { best = r; bt = t; }   // strict > : first-max tie rule
        }
        __syncthreads();
    }
    if (tid == 0) {
        sTop = bt;
        atomicExch(&g_used[bt], 1);
    }
    __syncthreads();
    int top = sTop;

    // gather chosen bus output row (1024 floats, float4 x 1 per thread)
    const float4* src = reinterpret_cast<const float4*>(
        bus_outputs + ((size_t)top * N_TOK + n) * LAT);
    float4* dst = reinterpret_cast<float4*>(g_bus_context + (size_t)n * LAT);
    dst[tid] = src[tid];
}

// ---------------------------------------------------------------------------
// 2) keep_mask
// ---------------------------------------------------------------------------
__global__ void keep_kernel(float* __restrict__ out_keep) {
    if (threadIdx.x < T_MSG)
        out_keep[threadIdx.x] = (g_used[threadIdx.x] == 0) ? 1.0f : 0.0f;
}

// ---------------------------------------------------------------------------
// 3) codebook row norms
// ---------------------------------------------------------------------------
__global__ void cnorm_kernel(const float* __restrict__ codebook) {
    int c = blockIdx.x * (blockDim.x >> 5) + (threadIdx.x >> 5);
    int lane = threadIdx.x & 31;
    if (c >= NC) return;
    float s = 0.f;
    const float* row = codebook + (size_t)c * SYM;
    #pragma unroll
    for (int i = 0; i < SYM / 32; i++) {
        float v = row[lane + i * 32];
        s += v * v;
    }
    #pragma unroll
    for (int off = 16; off > 0; off >>= 1)
        s += __shfl_down_sync(0xffffffffu, s, off);
    if (lane == 0) g_cnorm[c] = s;
}

// ---------------------------------------------------------------------------
// 4) Generic tiled SGEMM:
//      C = alpha * (A @ opB(B)) + bias[n]  (+ residual[m,n])  (relu)
//    A = [A1 | A2] concatenated along K (A2 may be null when K1 == K).
//    All dims multiples of 64 (M,N) and 16 (K); no bounds checks needed.
// ---------------------------------------------------------------------------
template <bool B_TRANS, bool RELU, bool HAS_RES>
__global__ __launch_bounds__(256)
void sgemm_kernel(const float* __restrict__ A1, const float* __restrict__ A2,
                  int K1, int K,
                  const float* __restrict__ B, int ldb,
                  const float* __restrict__ bias, float alpha,
                  const float* __restrict__ residual,
                  float* __restrict__ C, int M, int N) {
    constexpr int BM = 64, BN = 64, BK = 16;
    __shared__ float As[BK][BM];
    __shared__ float Bs[BK][BN];

    int tid = threadIdx.x;
    int m0 = blockIdx.y * BM;
    int n0 = blockIdx.x * BN;
    int ty = tid >> 4, tx = tid & 15;

    float acc[4][4];
    #pragma unroll
    for (int i = 0; i < 4; i++)
        #pragma unroll
        for (int j = 0; j < 4; j++) acc[i][j] = 0.f;

    for (int k0 = 0; k0 < K; k0 += BK) {
        // --- load A tile (handles concat split; BK divides K1) ---
        {
            const float* Ap; int acol, lda;
            if (k0 < K1) { Ap = A1; acol = k0; lda = K1; }
            else         { Ap = A2; acol = k0 - K1; lda = K - K1; }
            int r = tid >> 2, c = (tid & 3) * 4;
            float4 v = *reinterpret_cast<const float4*>(
                Ap + (size_t)(m0 + r) * lda + acol + c);
            As[c + 0][r] = v.x; As[c + 1][r] = v.y;
            As[c + 2][r] = v.z; As[c + 3][r] = v.w;
        }
        // --- load B tile ---
        if (!B_TRANS) {
            int r = tid >> 4, c = (tid & 15) * 4;
            float4 v = *reinterpret_cast<const float4*>(
                B + (size_t)(k0 + r) * ldb + n0 + c);
            *reinterpret_cast<float4*>(&Bs[r][c]) = v;
        } else {
            int r = tid >> 2, c = (tid & 3) * 4;   // r = n within tile, c = k
            float4 v = *reinterpret_cast<const float4*>(
                B + (size_t)(n0 + r) * ldb + k0 + c);
            Bs[c + 0][r] = v.x; Bs[c + 1][r] = v.y;
            Bs[c + 2][r] = v.z; Bs[c + 3][r] = v.w;
        }
        __syncthreads();

        #pragma unroll
        for (int k = 0; k < BK; k++) {
            float a[4], b[4];
            *reinterpret_cast<float4*>(a) =
                *reinterpret_cast<const float4*>(&As[k][ty * 4]);
            *reinterpret_cast<float4*>(b) =
                *reinterpret_cast<const float4*>(&Bs[k][tx * 4]);
            #pragma unroll
            for (int i = 0; i < 4; i++)
                #pragma unroll
                for (int j = 0; j < 4; j++)
                    acc[i][j] += a[i] * b[j];
        }
        __syncthreads();
    }

    // epilogue
    #pragma unroll
    for (int i = 0; i < 4; i++) {
        int m = m0 + ty * 4 + i;
        float4 o;
        float* po = &o.x;
        #pragma unroll
        for (int j = 0; j < 4; j++) {
            int n = n0 + tx * 4 + j;
            float v = alpha * acc[i][j] + bias[n];
            if (HAS_RES) v += residual[(size_t)m * N + n];
            if (RELU) v = fmaxf(v, 0.f);
            po[j] = v;
        }
        *reinterpret_cast<float4*>(C + (size_t)m * N + n0 + tx * 4) = o;
    }
}

// ---------------------------------------------------------------------------
// 5) VQ argmin over scores + gather quantized + write index (as float)
//    warp per token; block = 8 tokens
// ---------------------------------------------------------------------------
__global__ void argmin_gather_kernel(const float* __restrict__ codebook,
                                     float* __restrict__ out_quant,
                                     float* __restrict__ out_idx) {
    int warp = threadIdx.x >> 5, lane = threadIdx.x & 31;
    int n = blockIdx.x * 8 + warp;

    const float* sc = g_scores + (size_t)n * NC;
    float best = 3.4e38f;
    int bi = 0;
    #pragma unroll
    for (int w = 0; w < NC / 32; w++) {
        int c = lane + w * 32;
        float v = sc[c];
        if (v < best) { best = v; bi = c; }   // ascending scan: first-min in lane
    }
    #pragma unroll
    for (int off = 16; off > 0; off >>= 1) {
        float ov = __shfl_xor_sync(0xffffffffu, best, off);
        int   oi = __shfl_xor_sync(0xffffffffu, bi, off);
        if (ov < best || (ov == best && oi < bi)) { best = ov; bi = oi; }
    }
    if (lane == 0) out_idx[n] = (float)bi;

    const float* crow = codebook + (size_t)bi * SYM;
    float* qrow = out_quant + (size_t)n * SYM;
    #pragma unroll
    for (int j = 0; j < SYM / 32; j++)
        qrow[lane + j * 32] = crow[lane + j * 32];
}

// ---------------------------------------------------------------------------
// Launch
// ---------------------------------------------------------------------------
extern "C" void kernel_launch(void* const* d_in, const int* in_sizes, int n_in,
                              void* d_out, int out_size) {
    const float* token_state = (const float*)d_in[0];
    const float* bus_symbols = (const float*)d_in[1];
    // d_in[2] = bus_indices (unused), d_in[4] = bus_mask (unused)
    const float* bus_outputs = (const float*)d_in[3];
    const float* Wq    = (const float*)d_in[5];
    const float* bq    = (const float*)d_in[6];
    const float* Wread = (const float*)d_in[7];
    const float* bread = (const float*)d_in[8];
    const float* Wsym  = (const float*)d_in[9];
    const float* bsym  = (const float*)d_in[10];
    const float* Wc1   = (const float*)d_in[11];
    const float* bc1   = (const float*)d_in[12];
    const float* Wc2   = (const float*)d_in[13];
    const float* bc2   = (const float*)d_in[14];
    const float* codebook = (const float*)d_in[15];

    float* out = (float*)d_out;
    float* out_node  = out + OUT_NODE_OFF;
    float* out_quant = out + OUT_QUANT_OFF;
    float* out_idx   = out + OUT_IDX_OFF;
    float* out_keep  = out + OUT_KEEP_OFF;

    // scratch pointers
    float *p_ctx, *p_zread, *p_h, *p_raw, *p_scores, *p_cnorm;
    cudaGetSymbolAddress((void**)&p_ctx,    g_bus_context);
    cudaGetSymbolAddress((void**)&p_zread,  g_zread);
    cudaGetSymbolAddress((void**)&p_h,      g_h);
    cudaGetSymbolAddress((void**)&p_raw,    g_raw);
    cudaGetSymbolAddress((void**)&p_scores, g_scores);
    cudaGetSymbolAddress((void**)&p_cnorm,  g_cnorm);

    // 0) reset used flags
    init_used_kernel<<<1, 32>>>();

    // 1) routing + gather bus_context
    routing_kernel<<<N_TOK, 256>>>(bus_symbols, bus_outputs, Wq, bq);

    // 3) codebook norms (independent; run early)
    cnorm_kernel<<<NC / 8, 256>>>(codebook);

    // 4a) z_read = [token_state | bus_context] @ Wread + bread
    {
        dim3 grid(LAT / 64, N_TOK / 64);
        sgemm_kernel<false, false, false><<<grid, 256>>>(
            token_state, p_ctx, LAT, 2 * LAT,
            Wread, LAT, bread, 1.0f, nullptr, p_zread, N_TOK, LAT);
    }
    // 4b) raw_symbol = z_read @ Wsym + bsym
    {
        dim3 grid(SYM / 64, N_TOK / 64);
        sgemm_kernel<false, false, false><<<grid, 256>>>(
            p_zread, nullptr, LAT, LAT,
            Wsym, SYM, bsym, 1.0f, nullptr, p_raw, N_TOK, SYM);
    }
    // 4c) scores = -2 * raw @ codebook^T + ||c||^2   (argmin-equivalent d2)
    {
        dim3 grid(NC / 64, N_TOK / 64);
        sgemm_kernel<true, false, false><<<grid, 256>>>(
            p_raw, nullptr, SYM, SYM,
            codebook, SYM, p_cnorm, -2.0f, nullptr, p_scores, N_TOK, NC);
    }
    // 5) argmin + gather quantized + indices
    argmin_gather_kernel<<<N_TOK / 8, 256>>>(codebook, out_quant, out_idx);

    // 4d) h = relu([z_read | quantized] @ Wc1 + bc1)
    {
        dim3 grid(LAT / 64, N_TOK / 64);
        sgemm_kernel<false, true, false><<<grid, 256>>>(
            p_zread, out_quant, LAT, LAT + SYM,
            Wc1, LAT, bc1, 1.0f, nullptr, p_h, N_TOK, LAT);
    }
    // 4e) node_output = h @ Wc2 + bc2 + token_state
    {
        dim3 grid(LAT / 64, N_TOK / 64);
        sgemm_kernel<false, false, true><<<grid, 256>>>(
            p_h, nullptr, LAT, LAT,
            Wc2, LAT, bc2, 1.0f, token_state, out_node, N_TOK, LAT);
    }
    // 2) keep_mask
    keep_kernel<<<1, 32>>>(out_keep);
}

// round 3
// speedup vs baseline: 1.5387x; 1.5387x over previous
#include <cuda_runtime.h>
#include <cstdint>

// ---------------------------------------------------------------------------
// Problem constants
// ---------------------------------------------------------------------------
#define T_MSG 8
#define N_TOK 8192
#define LAT 1024
#define SYM 256
#define NC 512

#define OUT_QUANT_OFF ((size_t)N_TOK * LAT)
#define OUT_IDX_OFF   (OUT_QUANT_OFF + (size_t)N_TOK * SYM)
#define OUT_KEEP_OFF  (OUT_IDX_OFF + (size_t)N_TOK)

// ---------------------------------------------------------------------------
// Device scratch (hi/lo tf32-split pairs for every GEMM operand)
// ---------------------------------------------------------------------------
__device__ float g_ts_h[(size_t)N_TOK * LAT];
__device__ float g_ts_l[(size_t)N_TOK * LAT];
__device__ float g_ctx_h[(size_t)N_TOK * LAT];
__device__ float g_ctx_l[(size_t)N_TOK * LAT];
__device__ float g_z_h[(size_t)N_TOK * LAT];
__device__ float g_z_l[(size_t)N_TOK * LAT];
__device__ float g_h_h[(size_t)N_TOK * LAT];
__device__ float g_h_l[(size_t)N_TOK * LAT];
__device__ float g_raw_h[(size_t)N_TOK * SYM];
__device__ float g_raw_l[(size_t)N_TOK * SYM];
__device__ float g_q_h[(size_t)N_TOK * SYM];
__device__ float g_q_l[(size_t)N_TOK * SYM];
__device__ float g_scores[(size_t)N_TOK * NC];
__device__ float g_cnorm[NC];
__device__ int   g_used[T_MSG];

__device__ float g_wread_h[(size_t)LAT * 2 * LAT];
__device__ float g_wread_l[(size_t)LAT * 2 * LAT];
__device__ float g_wc1_h[(size_t)LAT * (LAT + SYM)];
__device__ float g_wc1_l[(size_t)LAT * (LAT + SYM)];
__device__ float g_wc2_h[(size_t)LAT * LAT];
__device__ float g_wc2_l[(size_t)LAT * LAT];
__device__ float g_wsym_h[(size_t)SYM * LAT];
__device__ float g_wsym_l[(size_t)SYM * LAT];
__device__ float g_cb_h[(size_t)NC * SYM];
__device__ float g_cb_l[(size_t)NC * SYM];

// ---------------------------------------------------------------------------
// Helpers
// ---------------------------------------------------------------------------
__device__ __forceinline__ float tf32_rn(float x) {
    uint32_t u;
    asm("cvt.rna.tf32.f32 %0, %1;" : "=r"(u) : "f"(x));
    return __uint_as_float(u);
}
__device__ __forceinline__ uint32_t smem_u32(const void* p) {
    uint32_t a;
    asm("{ .reg .u64 t; cvta.to.shared.u64 t, %1; cvt.u32.u64 %0, t; }"
        : "=r"(a) : "l"(p));
    return a;
}
__device__ __forceinline__ void cp16(uint32_t dst, const void* src) {
    asm volatile("cp.async.cg.shared.global [%0], [%1], 16;"
                 :: "r"(dst), "l"(src));
}
#define CP_COMMIT() asm volatile("cp.async.commit_group;" ::: "memory")
#define CP_WAIT1()  asm volatile("cp.async.wait_group 1;" ::: "memory")

#define MMA8(d, a, b) \
    asm volatile( \
        "mma.sync.aligned.m16n8k8.row.col.f32.tf32.tf32.f32 " \
        "{%0,%1,%2,%3}, {%4,%5,%6,%7}, {%8,%9}, {%0,%1,%2,%3};" \
        : "+f"((d)[0]), "+f"((d)[1]), "+f"((d)[2]), "+f"((d)[3]) \
        : "r"((a)[0]), "r"((a)[1]), "r"((a)[2]), "r"((a)[3]), \
          "r"((b)[0]), "r"((b)[1]))

// ---------------------------------------------------------------------------
// tf32x3 mma.sync GEMM:  Out = alpha*(A @ B^T) + bias (+res)(relu)
// A = [A1|A2] along K, pre-split hi/lo [M,K]; B pre-split hi/lo [N,K].
// CTA tile 128x128, BK=32, 8 warps (4x2), warp tile 32x64.
// SMEM rows padded to 36 floats (conflict-free frag loads).
// ---------------------------------------------------------------------------
#define STG_F 18432                 // floats per stage: 4 arrays * 128*36
#define SMEM_BYTES (2 * STG_F * 4)  // 147456

template <bool SPLIT, bool RELU, bool HAS_RES>
__global__ __launch_bounds__(256, 1)
void tgemm_mma(const float* __restrict__ A1h, const float* __restrict__ A1l,
               const float* __restrict__ A2h, const float* __restrict__ A2l,
               int K1, int K,
               const float* __restrict__ Bh, const float* __restrict__ Bl,
               const float* __restrict__ bias, float alpha,
               const float* __restrict__ residual,
               float* __restrict__ O0, float* __restrict__ O1, int Ntot) {
    extern __shared__ __align__(16) float smf[];
    const int tid = threadIdx.x;
    const int lane = tid & 31, wid = tid >> 5;
    const int wm = wid >> 1, wn = wid & 1;
    const int m0 = blockIdx.y << 7, n0 = blockIdx.x << 7;
    const uint32_t sbase = smem_u32(smf);

    float acc[2][8][4];
    #pragma unroll
    for (int mi = 0; mi < 2; mi++)
        #pragma unroll
        for (int ni = 0; ni < 8; ni++)
            #pragma unroll
            for (int r = 0; r < 4; r++) acc[mi][ni][r] = 0.f;

    const int nc = K >> 5;

    // ---- staging (cp.async) ----
    auto stage = [&](int s, int c) {
        const int k0 = c << 5;
        const uint32_t sb = sbase + (uint32_t)s * STG_F * 4;
        #pragma unroll
        for (int it = 0; it < 4; ++it) {
            int idx = tid + (it << 8);
            int row = idx >> 3, seg = idx & 7;
            int kk = k0 + (seg << 2);
            const float *ph, *pl;
            if (kk < K1) {
                size_t o = (size_t)(m0 + row) * K1 + kk;
                ph = A1h + o; pl = A1l + o;
            } else {
                size_t o = (size_t)(m0 + row) * (K - K1) + (kk - K1);
                ph = A2h + o; pl = A2l + o;
            }
            uint32_t d = sb + (uint32_t)(row * 36 + (seg << 2)) * 4;
            cp16(d, ph);
            cp16(d + 4608 * 4, pl);
        }
        #pragma unroll
        for (int it = 0; it < 4; ++it) {
            int idx = tid + (it << 8);
            int row = idx >> 3, seg = idx & 7;
            size_t o = (size_t)(n0 + row) * K + k0 + (seg << 2);
            uint32_t d = sb + (uint32_t)(9216 + row * 36 + (seg << 2)) * 4;
            cp16(d, Bh + o);
            cp16(d + 4608 * 4, Bl + o);
        }
    };

    stage(0, 0);
    CP_COMMIT();

    const int am = (wm << 5) + (lane >> 2);
    const int bn = (wn << 6) + (lane >> 2);
    const int kb = lane & 3;

    for (int c = 0; c < nc; ++c) {
        if (c + 1 < nc) stage((c + 1) & 1, c + 1);
        CP_COMMIT();
        CP_WAIT1();
        __syncthreads();

        const float* base = smf + (c & 1) * STG_F;
        const float* sAh = base;
        const float* sAl = base + 4608;
        const float* sBh = base + 9216;
        const float* sBl = base + 13824;

        #pragma unroll
        for (int k8 = 0; k8 < 4; ++k8) {
            const int ko = (k8 << 3) + kb;
            uint32_t ah[2][4], al[2][4], bh[8][2], bl[8][2];
            #pragma unroll
            for (int mi = 0; mi < 2; mi++) {
                const float* p = sAh + (am + (mi << 4)) * 36 + ko;
                ah[mi][0] = __float_as_uint(p[0]);
                ah[mi][1] = __float_as_uint(p[288]);
                ah[mi][2] = __float_as_uint(p[4]);
                ah[mi][3] = __float_as_uint(p[292]);
                const float* q = sAl + (am + (mi << 4)) * 36 + ko;
                al[mi][0] = __float_as_uint(q[0]);
                al[mi][1] = __float_as_uint(q[288]);
                al[mi][2] = __float_as_uint(q[4]);
                al[mi][3] = __float_as_uint(q[292]);
            }
            #pragma unroll
            for (int ni = 0; ni < 8; ni++) {
                const float* p = sBh + (bn + (ni << 3)) * 36 + ko;
                bh[ni][0] = __float_as_uint(p[0]);
                bh[ni][1] = __float_as_uint(p[4]);
                const float* q = sBl + (bn + (ni << 3)) * 36 + ko;
                bl[ni][0] = __float_as_uint(q[0]);
                bl[ni][1] = __float_as_uint(q[4]);
            }
            // 3 passes; same acc revisited every 16 mmas (hides RAW latency)
            #pragma unroll
            for (int mi = 0; mi < 2; mi++)
                #pragma unroll
                for (int ni = 0; ni < 8; ni++) MMA8(acc[mi][ni], ah[mi], bh[ni]);
            #pragma unroll
            for (int mi = 0; mi < 2; mi++)
                #pragma unroll
                for (int ni = 0; ni < 8; ni++) MMA8(acc[mi][ni], ah[mi], bl[ni]);
            #pragma unroll
            for (int mi = 0; mi < 2; mi++)
                #pragma unroll
                for (int ni = 0; ni < 8; ni++) MMA8(acc[mi][ni], al[mi], bh[ni]);
        }
        __syncthreads();
    }

    // ---- epilogue ----
    #pragma unroll
    for (int mi = 0; mi < 2; mi++) {
        #pragma unroll
        for (int ni = 0; ni < 8; ni++) {
            int r = m0 + (wm << 5) + (mi << 4) + (lane >> 2);
            int nn = n0 + (wn << 6) + (ni << 3) + ((lane & 3) << 1);
            float b0 = bias[nn], b1 = bias[nn + 1];
            #pragma unroll
            for (int half = 0; half < 2; half++) {
                int rr = r + half * 8;
                float v0 = alpha * acc[mi][ni][half * 2 + 0] + b0;
                float v1 = alpha * acc[mi][ni][half * 2 + 1] + b1;
                if (HAS_RES) {
                    const float2 rv = *reinterpret_cast<const float2*>(
                        residual + (size_t)rr * Ntot + nn);
                    v0 += rv.x; v1 += rv.y;
                }
                if (RELU) { v0 = fmaxf(v0, 0.f); v1 = fmaxf(v1, 0.f); }
                if (SPLIT) {
                    float h0 = tf32_rn(v0), h1 = tf32_rn(v1);
                    float l0 = tf32_rn(v0 - h0), l1 = tf32_rn(v1 - h1);
                    *reinterpret_cast<float2*>(O0 + (size_t)rr * Ntot + nn) =
                        make_float2(h0, h1);
                    *reinterpret_cast<float2*>(O1 + (size_t)rr * Ntot + nn) =
                        make_float2(l0, l1);
                } else {
                    *reinterpret_cast<float2*>(O0 + (size_t)rr * Ntot + nn) =
                        make_float2(v0, v1);
                }
            }
        }
    }
}

// ---------------------------------------------------------------------------
// Prep / small kernels
// ---------------------------------------------------------------------------
__global__ void init_used_kernel() {
    if (threadIdx.x < T_MSG) g_used[threadIdx.x] = 0;
}

__global__ void split4_kernel(const float* __restrict__ in,
                              float* __restrict__ hi, float* __restrict__ lo) {
    int i = blockIdx.x * 256 + threadIdx.x;
    float4 v = reinterpret_cast<const float4*>(in)[i];
    float4 h, l;
    h.x = tf32_rn(v.x); l.x = tf32_rn(v.x - h.x);
    h.y = tf32_rn(v.y); l.y = tf32_rn(v.y - h.y);
    h.z = tf32_rn(v.z); l.z = tf32_rn(v.z - h.z);
    h.w = tf32_rn(v.w); l.w = tf32_rn(v.w - h.w);
    reinterpret_cast<float4*>(hi)[i] = h;
    reinterpret_cast<float4*>(lo)[i] = l;
}

__global__ void routing_kernel(const float* __restrict__ bus_symbols,
                               const float* __restrict__ bus_outputs,
                               const float* __restrict__ Wq,
                               const float* __restrict__ bq) {
    int n = blockIdx.x;
    int tid = threadIdx.x;
    int lane = tid & 31, warp = tid >> 5;
    __shared__ float sWq[SYM];
    __shared__ float sRed[8];
    __shared__ int sTop;
    sWq[tid] = Wq[tid];
    __syncthreads();
    float best = -3.4e38f;
    int bt = 0;
    for (int t = 0; t < T_MSG; t++) {
        float v = bus_symbols[((size_t)t * N_TOK + n) * SYM + tid] * sWq[tid];
        #pragma unroll
        for (int off = 16; off > 0; off >>= 1)
            v += __shfl_down_sync(0xffffffffu, v, off);
        if (lane == 0) sRed[warp] = v;
        __syncthreads();
        if (tid == 0) {
            float r = sRed[0] + sRed[1] + sRed[2] + sRed[3]
                    + sRed[4] + sRed[5] + sRed[6] + sRed[7] + bq[0];
            if (r > best) { best = r; bt = t; }
        }
        __syncthreads();
    }
    if (tid == 0) { sTop = bt; atomicExch(&g_used[bt], 1); }
    __syncthreads();
    int top = sTop;
    const float4* src = reinterpret_cast<const float4*>(
        bus_outputs + ((size_t)top * N_TOK + n) * LAT);
    float4 v = src[tid];
    float4 h, l;
    h.x = tf32_rn(v.x); l.x = tf32_rn(v.x - h.x);
    h.y = tf32_rn(v.y); l.y = tf32_rn(v.y - h.y);
    h.z = tf32_rn(v.z); l.z = tf32_rn(v.z - h.z);
    h.w = tf32_rn(v.w); l.w = tf32_rn(v.w - h.w);
    reinterpret_cast<float4*>(g_ctx_h + (size_t)n * LAT)[tid] = h;
    reinterpret_cast<float4*>(g_ctx_l + (size_t)n * LAT)[tid] = l;
}

__global__ void keep_kernel(float* __restrict__ out_keep) {
    if (threadIdx.x < T_MSG)
        out_keep[threadIdx.x] = (g_used[threadIdx.x] == 0) ? 1.0f : 0.0f;
}

__global__ void cnorm_kernel(const float* __restrict__ codebook) {
    int c = blockIdx.x * (blockDim.x >> 5) + (threadIdx.x >> 5);
    int lane = threadIdx.x & 31;
    if (c >= NC) return;
    float s = 0.f;
    const float* row = codebook + (size_t)c * SYM;
    #pragma unroll
    for (int i = 0; i < SYM / 32; i++) {
        float v = row[lane + i * 32];
        s += v * v;
    }
    #pragma unroll
    for (int off = 16; off > 0; off >>= 1)
        s += __shfl_down_sync(0xffffffffu, s, off);
    if (lane == 0) g_cnorm[c] = s;
}

// transpose + tf32 split: W [K,N] -> hi/lo [N,K]
__global__ void wprep_T(const float* __restrict__ W, int K, int N,
                        float* __restrict__ hi, float* __restrict__ lo) {
    __shared__ float t[32][33];
    int k0 = blockIdx.y << 5, n0 = blockIdx.x << 5;
    int tx = threadIdx.x, ty = threadIdx.y;
    #pragma unroll
    for (int i = 0; i < 32; i += 8)
        t[ty + i][tx] = W[(size_t)(k0 + ty + i) * N + n0 + tx];
    __syncthreads();
    #pragma unroll
    for (int i = 0; i < 32; i += 8) {
        int n = n0 + ty + i, k = k0 + tx;
        float v = t[tx][ty + i];
        float h = tf32_rn(v);
        hi[(size_t)n * K + k] = h;
        lo[(size_t)n * K + k] = tf32_rn(v - h);
    }
}

__global__ void argmin_gather_kernel(const float* __restrict__ codebook,
                                     float* __restrict__ out_quant,
                                     float* __restrict__ out_idx) {
    int warp = threadIdx.x >> 5, lane = threadIdx.x & 31;
    int n = blockIdx.x * 8 + warp;
    const float* sc = g_scores + (size_t)n * NC;
    float best = 3.4e38f;
    int bi = 0;
    #pragma unroll
    for (int w = 0; w < NC / 32; w++) {
        int c = lane + w * 32;
        float v = sc[c];
        if (v < best) { best = v; bi = c; }
    }
    #pragma unroll
    for (int off = 16; off > 0; off >>= 1) {
        float ov = __shfl_xor_sync(0xffffffffu, best, off);
        int   oi = __shfl_xor_sync(0xffffffffu, bi, off);
        if (ov < best || (ov == best && oi < bi)) { best = ov; bi = oi; }
    }
    bi = __shfl_sync(0xffffffffu, bi, 0);
    if (lane == 0) out_idx[n] = (float)bi;
    const float* crow = codebook + (size_t)bi * SYM;
    const float* ch = g_cb_h + (size_t)bi * SYM;
    const float* cl = g_cb_l + (size_t)bi * SYM;
    float* qrow = out_quant + (size_t)n * SYM;
    float* qh = g_q_h + (size_t)n * SYM;
    float* ql = g_q_l + (size_t)n * SYM;
    #pragma unroll
    for (int j = 0; j < SYM / 32; j++) {
        int c = lane + j * 32;
        qrow[c] = crow[c];
        qh[c] = ch[c];
        ql[c] = cl[c];
    }
}

// ---------------------------------------------------------------------------
// Launch
// ---------------------------------------------------------------------------
extern "C" void kernel_launch(void* const* d_in, const int* in_sizes, int n_in,
                              void* d_out, int out_size) {
    const float* token_state = (const float*)d_in[0];
    const float* bus_symbols = (const float*)d_in[1];
    const float* bus_outputs = (const float*)d_in[3];
    const float* Wq    = (const float*)d_in[5];
    const float* bq    = (const float*)d_in[6];
    const float* Wread = (const float*)d_in[7];
    const float* bread = (const float*)d_in[8];
    const float* Wsym  = (const float*)d_in[9];
    const float* bsym  = (const float*)d_in[10];
    const float* Wc1   = (const float*)d_in[11];
    const float* bc1   = (const float*)d_in[12];
    const float* Wc2   = (const float*)d_in[13];
    const float* bc2   = (const float*)d_in[14];
    const float* codebook = (const float*)d_in[15];

    float* out = (float*)d_out;
    float* out_node  = out;
    float* out_quant = out + OUT_QUANT_OFF;
    float* out_idx   = out + OUT_IDX_OFF;
    float* out_keep  = out + OUT_KEEP_OFF;

    #define SYMADDR(p, s) cudaGetSymbolAddress((void**)&p, s)
    float *p_tsh, *p_tsl, *p_ctxh, *p_ctxl, *p_zh, *p_zl, *p_hh, *p_hl;
    float *p_rawh, *p_rawl, *p_qh, *p_ql, *p_scores, *p_cnorm;
    float *p_wrh, *p_wrl, *p_w1h, *p_w1l, *p_w2h, *p_w2l, *p_wsh, *p_wsl;
    float *p_cbh, *p_cbl;
    SYMADDR(p_tsh, g_ts_h);   SYMADDR(p_tsl, g_ts_l);
    SYMADDR(p_ctxh, g_ctx_h); SYMADDR(p_ctxl, g_ctx_l);
    SYMADDR(p_zh, g_z_h);     SYMADDR(p_zl, g_z_l);
    SYMADDR(p_hh, g_h_h);     SYMADDR(p_hl, g_h_l);
    SYMADDR(p_rawh, g_raw_h); SYMADDR(p_rawl, g_raw_l);
    SYMADDR(p_qh, g_q_h);     SYMADDR(p_ql, g_q_l);
    SYMADDR(p_scores, g_scores);
    SYMADDR(p_cnorm, g_cnorm);
    SYMADDR(p_wrh, g_wread_h); SYMADDR(p_wrl, g_wread_l);
    SYMADDR(p_w1h, g_wc1_h);   SYMADDR(p_w1l, g_wc1_l);
    SYMADDR(p_w2h, g_wc2_h);   SYMADDR(p_w2l, g_wc2_l);
    SYMADDR(p_wsh, g_wsym_h);  SYMADDR(p_wsl, g_wsym_l);
    SYMADDR(p_cbh, g_cb_h);    SYMADDR(p_cbl, g_cb_l);

    cudaFuncSetAttribute(tgemm_mma<true, false, false>,
                         cudaFuncAttributeMaxDynamicSharedMemorySize, SMEM_BYTES);
    cudaFuncSetAttribute(tgemm_mma<false, false, false>,
                         cudaFuncAttributeMaxDynamicSharedMemorySize, SMEM_BYTES);
    cudaFuncSetAttribute(tgemm_mma<true, true, false>,
                         cudaFuncAttributeMaxDynamicSharedMemorySize, SMEM_BYTES);
    cudaFuncSetAttribute(tgemm_mma<false, false, true>,
                         cudaFuncAttributeMaxDynamicSharedMemorySize, SMEM_BYTES);

    dim3 tpb(32, 8);

    init_used_kernel<<<1, 32>>>();
    routing_kernel<<<N_TOK, 256>>>(bus_symbols, bus_outputs, Wq, bq);
    cnorm_kernel<<<NC / 8, 256>>>(codebook);
    split4_kernel<<<(N_TOK * LAT / 4) / 256, 256>>>(token_state, p_tsh, p_tsl);

    wprep_T<<<dim3(LAT / 32, 2 * LAT / 32), tpb>>>(Wread, 2 * LAT, LAT, p_wrh, p_wrl);
    wprep_T<<<dim3(SYM / 32, LAT / 32), tpb>>>(Wsym, LAT, SYM, p_wsh, p_wsl);
    wprep_T<<<dim3(LAT / 32, (LAT + SYM) / 32), tpb>>>(Wc1, LAT + SYM, LAT, p_w1h, p_w1l);
    wprep_T<<<dim3(LAT / 32, LAT / 32), tpb>>>(Wc2, LAT, LAT, p_w2h, p_w2l);
    split4_kernel<<<(NC * SYM / 4) / 256, 256>>>(codebook, p_cbh, p_cbl);

    // z = [ts | ctx] @ Wread + bread    -> split
    tgemm_mma<true, false, false><<<dim3(LAT / 128, N_TOK / 128), 256, SMEM_BYTES>>>(
        p_tsh, p_tsl, p_ctxh, p_ctxl, LAT, 2 * LAT,
        p_wrh, p_wrl, bread, 1.0f, nullptr, p_zh, p_zl, LAT);
    // raw = z @ Wsym + bsym             -> split
    tgemm_mma<true, false, false><<<dim3(SYM / 128, N_TOK / 128), 256, SMEM_BYTES>>>(
        p_zh, p_zl, p_zh, p_zl, LAT, LAT,
        p_wsh, p_wsl, bsym, 1.0f, nullptr, p_rawh, p_rawl, SYM);
    // scores = -2 * raw @ cb^T + ||c||^2
    tgemm_mma<false, false, false><<<dim3(NC / 128, N_TOK / 128), 256, SMEM_BYTES>>>(
        p_rawh, p_rawl, p_rawh, p_rawl, SYM, SYM,
        p_cbh, p_cbl, p_cnorm, -2.0f, nullptr, p_scores, nullptr, NC);
    // argmin + quantized + indices
    argmin_gather_kernel<<<N_TOK / 8, 256>>>(codebook, out_quant, out_idx);
    // h = relu([z | quant] @ Wc1 + bc1) -> split
    tgemm_mma<true, true, false><<<dim3(LAT / 128, N_TOK / 128), 256, SMEM_BYTES>>>(
        p_zh, p_zl, p_qh, p_ql, LAT, LAT + SYM,
        p_w1h, p_w1l, bc1, 1.0f, nullptr, p_hh, p_hl, LAT);
    // node = h @ Wc2 + bc2 + token_state
    tgemm_mma<false, false, true><<<dim3(LAT / 128, N_TOK / 128), 256, SMEM_BYTES>>>(
        p_hh, p_hl, p_hh, p_hl, LAT, LAT,
        p_w2h, p_w2l, bc2, 1.0f, token_state, out_node, nullptr, LAT);

    keep_kernel<<<1, 32>>>(out_keep);
}